// round 10
// baseline (speedup 1.0000x reference)
#include <cuda_runtime.h>
#include <math_constants.h>

// ---------------------------------------------------------------------------
// GAT 2-layer forward, fixed shapes. CSR-based, zero float atomics.
//   N=100000, Fin=256, L1: H=4 x C=32 (F1=128 concat), L2: 1 x 64.
//   E=1.6M + N self loops.
// R9: gemm2 on tensor pipe (tf32 HMMA); k_l1/k_l2 softmax register-resident
//     (smem alpha broadcast, shuffle src ids), global ex arrays only as
//     deg>64 fallback.
// ---------------------------------------------------------------------------

#define NNODES 100000
#define E_IN   1600000
#define ETOT   (E_IN + NNODES)
#define NH1    4
#define F1     128
#define FIN    256
#define CO     64
#define EPSV   1e-16f
#define SCAN_B 512
#define NB1    ((NNODES + SCAN_B - 1) / SCAN_B)   // 196

static const int TPB = 256;

// ---------------- device scratch (static, 16B-aligned) ----------------------
__device__ __align__(16) float g_h1  [(size_t)NNODES * F1];
__device__ __align__(16) float g_agg1[(size_t)NNODES * F1];
__device__ __align__(16) float g_h2  [(size_t)NNODES * CO];
__device__ __align__(16) float g_asrc1[NNODES * NH1];
__device__ __align__(16) float g_adst1[NNODES * NH1];
__device__ __align__(16) float g_ex1 [(size_t)ETOT * NH1];   // deg>64 fallback only
__device__ __align__(16) float g_asrc2[NNODES];
__device__ __align__(16) float g_adst2[NNODES];
__device__ __align__(16) float g_ex2 [ETOT];                 // deg>64 fallback only
// CSR machinery
__device__ int g_esrc[ETOT];
__device__ int g_edst[ETOT];
__device__ int g_csrc[ETOT];
__device__ int g_deg [NNODES];
__device__ int g_scan[NNODES];
__device__ int g_boff[NB1 + 32];
__device__ int g_rowptr[NNODES + 1];
__device__ int g_wcur[NNODES];

// ---------------- helpers ----------------------------------------------------
__device__ __forceinline__ float lrelu(float v) { return v >= 0.f ? v : 0.2f * v; }
__device__ __forceinline__ float4 lrelu4(float4 v) {
    return make_float4(lrelu(v.x), lrelu(v.y), lrelu(v.z), lrelu(v.w));
}
__device__ __forceinline__ float4 max4(float4 a, float4 b) {
    return make_float4(fmaxf(a.x, b.x), fmaxf(a.y, b.y),
                       fmaxf(a.z, b.z), fmaxf(a.w, b.w));
}
__device__ __forceinline__ float4 exp4(float4 a, float4 m) {
    return make_float4(__expf(a.x - m.x), __expf(a.y - m.y),
                       __expf(a.z - m.z), __expf(a.w - m.w));
}
__device__ __forceinline__ float4 wred_max4(float4 v) {
#pragma unroll
    for (int o = 16; o > 0; o >>= 1) {
        v.x = fmaxf(v.x, __shfl_xor_sync(0xffffffffu, v.x, o));
        v.y = fmaxf(v.y, __shfl_xor_sync(0xffffffffu, v.y, o));
        v.z = fmaxf(v.z, __shfl_xor_sync(0xffffffffu, v.z, o));
        v.w = fmaxf(v.w, __shfl_xor_sync(0xffffffffu, v.w, o));
    }
    return v;
}
__device__ __forceinline__ float4 wred_sum4(float4 v) {
#pragma unroll
    for (int o = 16; o > 0; o >>= 1) {
        v.x += __shfl_xor_sync(0xffffffffu, v.x, o);
        v.y += __shfl_xor_sync(0xffffffffu, v.y, o);
        v.z += __shfl_xor_sync(0xffffffffu, v.z, o);
        v.w += __shfl_xor_sync(0xffffffffu, v.w, o);
    }
    return v;
}
__device__ __forceinline__ unsigned f2tf32(float f) {
    unsigned u;
    asm("cvt.rna.tf32.f32 %0, %1;" : "=r"(u) : "f"(f));
    return u;
}
__device__ __forceinline__ void mma_tf32(float4& d, const unsigned a[4],
                                         unsigned b0, unsigned b1) {
    asm volatile(
        "mma.sync.aligned.m16n8k8.row.col.f32.tf32.tf32.f32 "
        "{%0,%1,%2,%3}, {%4,%5,%6,%7}, {%8,%9}, {%0,%1,%2,%3};\n"
        : "+f"(d.x), "+f"(d.y), "+f"(d.z), "+f"(d.w)
        : "r"(a[0]), "r"(a[1]), "r"(a[2]), "r"(a[3]), "r"(b0), "r"(b1));
}

// ---------------- edge prep: dtype-robust decode + degree histogram ----------
__global__ void k_zero_deg() {
    int i = blockIdx.x * blockDim.x + threadIdx.x;
    if (i < NNODES) g_deg[i] = 0;
}
__global__ void k_prep(const void* __restrict__ ei_raw) {
    int e = blockIdx.x * blockDim.x + threadIdx.x;
    if (e >= ETOT) return;
    int s, d;
    if (e >= E_IN) {
        s = d = e - E_IN;
    } else {
        const long long* e64 = (const long long*)ei_raw;
        bool is64 = true;
#pragma unroll
        for (int q = 0; q < 4; q++) {
            long long v = e64[q];
            if (v < 0 || v >= NNODES) is64 = false;
        }
        if (is64) {
            s = (int)e64[e];
            d = (int)e64[(size_t)E_IN + e];
        } else {
            const int* e32 = (const int*)ei_raw;
            s = e32[e];
            d = e32[E_IN + e];
        }
    }
    g_esrc[e] = s;
    g_edst[e] = d;
    atomicAdd(&g_deg[d], 1);
}

// ---------------- 3-phase exclusive scan over degrees -------------------------
__global__ void __launch_bounds__(SCAN_B) k_scan1() {
    int t = threadIdx.x, b = blockIdx.x;
    int i = b * SCAN_B + t;
    int val = (i < NNODES) ? g_deg[i] : 0;
    int lane = t & 31, wid = t >> 5;
    int v = val;
#pragma unroll
    for (int o = 1; o < 32; o <<= 1) {
        int u = __shfl_up_sync(0xffffffffu, v, o);
        if (lane >= o) v += u;
    }
    __shared__ int wsum[SCAN_B / 32];
    if (lane == 31) wsum[wid] = v;
    __syncthreads();
    if (wid == 0) {
        int w = (lane < SCAN_B / 32) ? wsum[lane] : 0;
#pragma unroll
        for (int o = 1; o < 32; o <<= 1) {
            int u = __shfl_up_sync(0xffffffffu, w, o);
            if (lane >= o) w += u;
        }
        if (lane < SCAN_B / 32) wsum[lane] = w;
    }
    __syncthreads();
    int incl = v + (wid ? wsum[wid - 1] : 0);
    if (i < NNODES) g_scan[i] = incl;
    if (t == SCAN_B - 1) g_boff[b] = incl;
}
__global__ void k_scan2() {
    int t = threadIdx.x;
    int val = (t < NB1) ? g_boff[t] : 0;
    int lane = t & 31, wid = t >> 5;
    int v = val;
#pragma unroll
    for (int o = 1; o < 32; o <<= 1) {
        int u = __shfl_up_sync(0xffffffffu, v, o);
        if (lane >= o) v += u;
    }
    __shared__ int wsum[8];
    if (lane == 31) wsum[wid] = v;
    __syncthreads();
    if (wid == 0) {
        int w = (lane < 8) ? wsum[lane] : 0;
#pragma unroll
        for (int o = 1; o < 8; o <<= 1) {
            int u = __shfl_up_sync(0xffffffffu, w, o);
            if (lane >= o) w += u;
        }
        if (lane < 8) wsum[lane] = w;
    }
    __syncthreads();
    int incl = v + (wid ? wsum[wid - 1] : 0);
    if (t < NB1) g_boff[t] = incl - val;
}
__global__ void k_scan3() {
    int i = blockIdx.x * blockDim.x + threadIdx.x;
    if (i >= NNODES) return;
    int base = g_boff[i / SCAN_B];
    int excl = base + g_scan[i] - g_deg[i];
    g_rowptr[i] = excl;
    g_wcur[i]   = excl;
    if (i == 0) g_rowptr[NNODES] = ETOT;
}
__global__ void k_scatter() {
    int e = blockIdx.x * blockDim.x + threadIdx.x;
    if (e >= ETOT) return;
    int d = g_edst[e];
    int pos = atomicAdd(&g_wcur[d], 1);
    g_csrc[pos] = g_esrc[e];
}

// ---------------- gemm1: g_h1 = x[100000,256] @ W1[256,128], tf32 HMMA --------
__global__ void __launch_bounds__(256) gemm1_kernel(const float* __restrict__ A,
                                                    const float* __restrict__ B) {
    __shared__ unsigned As[128][36];
    __shared__ unsigned Bs[32][136];
    const int tid  = threadIdx.x;
    const int lane = tid & 31, wid = tid >> 5;
    const int wm = (wid & 3) * 32;
    const int wn = (wid >> 2) * 64;
    const int row0 = blockIdx.x * 128;
    const int g = lane >> 2, tg = lane & 3;

    float4 acc[2][8];
#pragma unroll
    for (int mt = 0; mt < 2; mt++)
#pragma unroll
        for (int nt = 0; nt < 8; nt++) acc[mt][nt] = make_float4(0, 0, 0, 0);

    for (int k0 = 0; k0 < FIN; k0 += 32) {
#pragma unroll
        for (int q = 0; q < 4; q++) {
            int f4 = tid + q * 256;
            int r = f4 >> 3, c = (f4 & 7) * 4;
            float4 v = make_float4(0, 0, 0, 0);
            int gr = row0 + r;
            if (gr < NNODES) v = *(const float4*)&A[(size_t)gr * FIN + k0 + c];
            *(uint4*)&As[r][c] =
                make_uint4(f2tf32(v.x), f2tf32(v.y), f2tf32(v.z), f2tf32(v.w));
        }
#pragma unroll
        for (int q = 0; q < 4; q++) {
            int f4 = tid + q * 256;
            int r = f4 >> 5, c = (f4 & 31) * 4;
            float4 v = *(const float4*)&B[(size_t)(k0 + r) * F1 + c];
            *(uint4*)&Bs[r][c] =
                make_uint4(f2tf32(v.x), f2tf32(v.y), f2tf32(v.z), f2tf32(v.w));
        }
        __syncthreads();

#pragma unroll
        for (int kk = 0; kk < 32; kk += 8) {
            unsigned a[2][4];
#pragma unroll
            for (int mt = 0; mt < 2; mt++) {
                int rb = wm + mt * 16;
                a[mt][0] = As[rb + g][kk + tg];
                a[mt][1] = As[rb + 8 + g][kk + tg];
                a[mt][2] = As[rb + g][kk + tg + 4];
                a[mt][3] = As[rb + 8 + g][kk + tg + 4];
            }
#pragma unroll
            for (int nt = 0; nt < 8; nt++) {
                unsigned b0 = Bs[kk + tg][wn + nt * 8 + g];
                unsigned b1 = Bs[kk + 4 + tg][wn + nt * 8 + g];
                mma_tf32(acc[0][nt], a[0], b0, b1);
                mma_tf32(acc[1][nt], a[1], b0, b1);
            }
        }
        __syncthreads();
    }

#pragma unroll
    for (int mt = 0; mt < 2; mt++) {
#pragma unroll
        for (int nt = 0; nt < 8; nt++) {
            int r = row0 + wm + mt * 16 + g;
            int c = wn + nt * 8 + tg * 2;
            if (r < NNODES)
                *(float2*)&g_h1[(size_t)r * F1 + c] =
                    make_float2(acc[mt][nt].x, acc[mt][nt].y);
            if (r + 8 < NNODES)
                *(float2*)&g_h1[(size_t)(r + 8) * F1 + c] =
                    make_float2(acc[mt][nt].z, acc[mt][nt].w);
        }
    }
}

// ---------------- gemm2: g_h2 = g_agg1[100000,128] @ W2[128,64], tf32 HMMA ----
// 128x64 tile, BK=32, 8 warps (4 along M x 2 along N), warp tile 32x32.
__global__ void __launch_bounds__(256) gemm2_kernel(const float* __restrict__ B) {
    __shared__ unsigned As[128][36];
    __shared__ unsigned Bs[32][72];
    const float* A = g_agg1;
    const int tid  = threadIdx.x;
    const int lane = tid & 31, wid = tid >> 5;
    const int wm = (wid & 3) * 32;
    const int wn = (wid >> 2) * 32;
    const int row0 = blockIdx.x * 128;
    const int g = lane >> 2, tg = lane & 3;

    float4 acc[2][4];
#pragma unroll
    for (int mt = 0; mt < 2; mt++)
#pragma unroll
        for (int nt = 0; nt < 4; nt++) acc[mt][nt] = make_float4(0, 0, 0, 0);

    for (int k0 = 0; k0 < F1; k0 += 32) {
#pragma unroll
        for (int q = 0; q < 4; q++) {
            int f4 = tid + q * 256;
            int r = f4 >> 3, c = (f4 & 7) * 4;
            float4 v = make_float4(0, 0, 0, 0);
            int gr = row0 + r;
            if (gr < NNODES) v = *(const float4*)&A[(size_t)gr * F1 + k0 + c];
            *(uint4*)&As[r][c] =
                make_uint4(f2tf32(v.x), f2tf32(v.y), f2tf32(v.z), f2tf32(v.w));
        }
#pragma unroll
        for (int q = 0; q < 2; q++) {
            int f4 = tid + q * 256;
            int r = f4 >> 4, c = (f4 & 15) * 4;
            float4 v = *(const float4*)&B[(size_t)(k0 + r) * CO + c];
            *(uint4*)&Bs[r][c] =
                make_uint4(f2tf32(v.x), f2tf32(v.y), f2tf32(v.z), f2tf32(v.w));
        }
        __syncthreads();

#pragma unroll
        for (int kk = 0; kk < 32; kk += 8) {
            unsigned a[2][4];
#pragma unroll
            for (int mt = 0; mt < 2; mt++) {
                int rb = wm + mt * 16;
                a[mt][0] = As[rb + g][kk + tg];
                a[mt][1] = As[rb + 8 + g][kk + tg];
                a[mt][2] = As[rb + g][kk + tg + 4];
                a[mt][3] = As[rb + 8 + g][kk + tg + 4];
            }
#pragma unroll
            for (int nt = 0; nt < 4; nt++) {
                unsigned b0 = Bs[kk + tg][wn + nt * 8 + g];
                unsigned b1 = Bs[kk + 4 + tg][wn + nt * 8 + g];
                mma_tf32(acc[0][nt], a[0], b0, b1);
                mma_tf32(acc[1][nt], a[1], b0, b1);
            }
        }
        __syncthreads();
    }

#pragma unroll
    for (int mt = 0; mt < 2; mt++) {
#pragma unroll
        for (int nt = 0; nt < 4; nt++) {
            int r = row0 + wm + mt * 16 + g;
            int c = wn + nt * 8 + tg * 2;
            if (r < NNODES)
                *(float2*)&g_h2[(size_t)r * CO + c] =
                    make_float2(acc[mt][nt].x, acc[mt][nt].y);
            if (r + 8 < NNODES)
                *(float2*)&g_h2[(size_t)(r + 8) * CO + c] =
                    make_float2(acc[mt][nt].z, acc[mt][nt].w);
        }
    }
}

// ---------------- attention coefficients --------------------------------------
__global__ void k_att1(const float* __restrict__ att_s,
                       const float* __restrict__ att_d) {
    __shared__ float ss[F1], sd[F1];
    if (threadIdx.x < F1) { ss[threadIdx.x] = att_s[threadIdx.x];
                            sd[threadIdx.x] = att_d[threadIdx.x]; }
    __syncthreads();
    int i = blockIdx.x * blockDim.x + threadIdx.x;
    if (i >= NNODES * NH1) return;
    int n = i >> 2, h = i & 3;
    const float4* hv = (const float4*)&g_h1[(size_t)n * F1 + h * 32];
    const float4* sv = (const float4*)&ss[h * 32];
    const float4* dv = (const float4*)&sd[h * 32];
    float s = 0.f, d = 0.f;
#pragma unroll
    for (int q = 0; q < 8; q++) {
        float4 hh = hv[q], a = sv[q], b = dv[q];
        s += hh.x * a.x + hh.y * a.y + hh.z * a.z + hh.w * a.w;
        d += hh.x * b.x + hh.y * b.y + hh.z * b.z + hh.w * b.w;
    }
    g_asrc1[i] = s;
    g_adst1[i] = d;
}

__global__ void k_att2(const float* __restrict__ att_s,
                       const float* __restrict__ att_d) {
    __shared__ float ss[CO], sd[CO];
    if (threadIdx.x < CO) { ss[threadIdx.x] = att_s[threadIdx.x];
                            sd[threadIdx.x] = att_d[threadIdx.x]; }
    __syncthreads();
    int n = blockIdx.x * blockDim.x + threadIdx.x;
    if (n >= NNODES) return;
    const float4* hv = (const float4*)&g_h2[(size_t)n * CO];
    const float4* sv = (const float4*)ss;
    const float4* dv = (const float4*)sd;
    float s = 0.f, d = 0.f;
#pragma unroll
    for (int q = 0; q < CO / 4; q++) {
        float4 hh = hv[q], a = sv[q], b = dv[q];
        s += hh.x * a.x + hh.y * a.y + hh.z * a.z + hh.w * a.w;
        d += hh.x * b.x + hh.y * b.y + hh.z * b.z + hh.w * b.w;
    }
    g_asrc2[n] = s;
    g_adst2[n] = d;
}

// ---------------- layer-1: fused softmax+aggregate, register-resident ---------
__global__ void __launch_bounds__(256) k_l1(const float* __restrict__ b1) {
    __shared__ float4 sal[8][64];   // per-warp normalized alpha (all 4 heads)
    int w = (blockIdx.x * blockDim.x + threadIdx.x) >> 5;
    if (w >= NNODES) return;
    const int n = w, lane = threadIdx.x & 31, ws = (threadIdx.x >> 5);
    const int beg = g_rowptr[n], end = g_rowptr[n + 1];
    const int deg = end - beg;
    const float4 ad = *(const float4*)&g_adst1[n * 4];
    const int h = lane >> 3;
    float4 acc = make_float4(0, 0, 0, 0);

    if (deg <= 64) {
        int s0 = 0, s1 = 0;
        float4 e0 = make_float4(0, 0, 0, 0), e1 = e0;
        const int p0 = beg + lane, p1 = p0 + 32;
        const bool v0 = p0 < end, v1 = p1 < end;
        float4 mx = make_float4(-CUDART_INF_F, -CUDART_INF_F,
                                -CUDART_INF_F, -CUDART_INF_F);
        if (v0) {
            s0 = g_csrc[p0];
            e0 = lrelu4(make_float4(g_asrc1[s0 * 4 + 0] + ad.x,
                                    g_asrc1[s0 * 4 + 1] + ad.y,
                                    g_asrc1[s0 * 4 + 2] + ad.z,
                                    g_asrc1[s0 * 4 + 3] + ad.w));
            mx = max4(mx, e0);
        }
        if (v1) {
            s1 = g_csrc[p1];
            e1 = lrelu4(make_float4(g_asrc1[s1 * 4 + 0] + ad.x,
                                    g_asrc1[s1 * 4 + 1] + ad.y,
                                    g_asrc1[s1 * 4 + 2] + ad.z,
                                    g_asrc1[s1 * 4 + 3] + ad.w));
            mx = max4(mx, e1);
        }
        mx = wred_max4(mx);
        float4 sm = make_float4(0, 0, 0, 0);
        float4 x0 = make_float4(0, 0, 0, 0), x1 = x0;
        if (v0) { x0 = exp4(e0, mx); sm.x += x0.x; sm.y += x0.y; sm.z += x0.z; sm.w += x0.w; }
        if (v1) { x1 = exp4(e1, mx); sm.x += x1.x; sm.y += x1.y; sm.z += x1.z; sm.w += x1.w; }
        sm = wred_sum4(sm);
        float4 inv = make_float4(1.f / (sm.x + EPSV), 1.f / (sm.y + EPSV),
                                 1.f / (sm.z + EPSV), 1.f / (sm.w + EPSV));
        if (v0) sal[ws][lane] = make_float4(x0.x * inv.x, x0.y * inv.y,
                                            x0.z * inv.z, x0.w * inv.w);
        if (v1) sal[ws][lane + 32] = make_float4(x1.x * inv.x, x1.y * inv.y,
                                                 x1.z * inv.z, x1.w * inv.w);
        __syncwarp();
        for (int j = 0; j < deg; j++) {
            int sv = (j < 32) ? s0 : s1;
            int s = __shfl_sync(0xffffffffu, sv, j & 31);
            float alpha = ((const float*)&sal[ws][j])[h];
            float4 hv = *(const float4*)&g_h1[(size_t)s * F1 + lane * 4];
            acc.x = fmaf(hv.x, alpha, acc.x);
            acc.y = fmaf(hv.y, alpha, acc.y);
            acc.z = fmaf(hv.z, alpha, acc.z);
            acc.w = fmaf(hv.w, alpha, acc.w);
        }
    } else {
        // rare fallback via global ex buffer
        float4 mx = make_float4(-CUDART_INF_F, -CUDART_INF_F,
                                -CUDART_INF_F, -CUDART_INF_F);
        for (int p = beg + lane; p < end; p += 32) {
            int s = g_csrc[p];
            float4 e = lrelu4(make_float4(g_asrc1[s * 4 + 0] + ad.x,
                                          g_asrc1[s * 4 + 1] + ad.y,
                                          g_asrc1[s * 4 + 2] + ad.z,
                                          g_asrc1[s * 4 + 3] + ad.w));
            *(float4*)&g_ex1[(size_t)p * 4] = e;
            mx = max4(mx, e);
        }
        mx = wred_max4(mx);
        float4 sm = make_float4(0, 0, 0, 0);
        for (int p = beg + lane; p < end; p += 32) {
            float4 e = *(const float4*)&g_ex1[(size_t)p * 4];
            float4 ex = exp4(e, mx);
            *(float4*)&g_ex1[(size_t)p * 4] = ex;
            sm.x += ex.x; sm.y += ex.y; sm.z += ex.z; sm.w += ex.w;
        }
        sm = wred_sum4(sm);
        float4 inv = make_float4(1.f / (sm.x + EPSV), 1.f / (sm.y + EPSV),
                                 1.f / (sm.z + EPSV), 1.f / (sm.w + EPSV));
        __syncwarp();
        const float invh = (h == 0) ? inv.x : (h == 1) ? inv.y
                         : (h == 2) ? inv.z : inv.w;
        for (int p = beg; p < end; ++p) {
            int s = g_csrc[p];
            float alpha = g_ex1[(size_t)p * 4 + h] * invh;
            float4 hv = *(const float4*)&g_h1[(size_t)s * F1 + lane * 4];
            acc.x = fmaf(hv.x, alpha, acc.x);
            acc.y = fmaf(hv.y, alpha, acc.y);
            acc.z = fmaf(hv.z, alpha, acc.z);
            acc.w = fmaf(hv.w, alpha, acc.w);
        }
    }

    float4 b = *(const float4*)&b1[lane * 4];
    float4 v = make_float4(acc.x + b.x, acc.y + b.y, acc.z + b.z, acc.w + b.w);
    v.x = v.x > 0.f ? v.x : expm1f(v.x);
    v.y = v.y > 0.f ? v.y : expm1f(v.y);
    v.z = v.z > 0.f ? v.z : expm1f(v.z);
    v.w = v.w > 0.f ? v.w : expm1f(v.w);
    *(float4*)&g_agg1[(size_t)n * F1 + lane * 4] = v;
}

// ---------------- layer-2: fused softmax+aggregate, register-resident ---------
__global__ void __launch_bounds__(256) k_l2(const float* __restrict__ b2,
                                            float* __restrict__ out) {
    __shared__ float sal[8][64];
    int w = (blockIdx.x * blockDim.x + threadIdx.x) >> 5;
    if (w >= NNODES) return;
    const int n = w, lane = threadIdx.x & 31, ws = (threadIdx.x >> 5);
    const int beg = g_rowptr[n], end = g_rowptr[n + 1];
    const int deg = end - beg;
    const float adn = g_adst2[n];
    float2 acc = make_float2(0, 0);

    if (deg <= 64) {
        int s0 = 0, s1 = 0;
        float e0 = 0.f, e1 = 0.f;
        const int p0 = beg + lane, p1 = p0 + 32;
        const bool v0 = p0 < end, v1 = p1 < end;
        float mx = -CUDART_INF_F;
        if (v0) { s0 = g_csrc[p0]; e0 = lrelu(g_asrc2[s0] + adn); mx = fmaxf(mx, e0); }
        if (v1) { s1 = g_csrc[p1]; e1 = lrelu(g_asrc2[s1] + adn); mx = fmaxf(mx, e1); }
#pragma unroll
        for (int o = 16; o > 0; o >>= 1)
            mx = fmaxf(mx, __shfl_xor_sync(0xffffffffu, mx, o));
        float sm = 0.f, x0 = 0.f, x1 = 0.f;
        if (v0) { x0 = __expf(e0 - mx); sm += x0; }
        if (v1) { x1 = __expf(e1 - mx); sm += x1; }
#pragma unroll
        for (int o = 16; o > 0; o >>= 1) sm += __shfl_xor_sync(0xffffffffu, sm, o);
        float inv = 1.f / (sm + EPSV);
        if (v0) sal[ws][lane]      = x0 * inv;
        if (v1) sal[ws][lane + 32] = x1 * inv;
        __syncwarp();
        for (int j = 0; j < deg; j++) {
            int sv = (j < 32) ? s0 : s1;
            int s = __shfl_sync(0xffffffffu, sv, j & 31);
            float alpha = sal[ws][j];
            float2 hv = *(const float2*)&g_h2[(size_t)s * CO + lane * 2];
            acc.x = fmaf(hv.x, alpha, acc.x);
            acc.y = fmaf(hv.y, alpha, acc.y);
        }
    } else {
        float mx = -CUDART_INF_F;
        for (int p = beg + lane; p < end; p += 32) {
            int s = g_csrc[p];
            float e = lrelu(g_asrc2[s] + adn);
            g_ex2[p] = e;
            mx = fmaxf(mx, e);
        }
#pragma unroll
        for (int o = 16; o > 0; o >>= 1)
            mx = fmaxf(mx, __shfl_xor_sync(0xffffffffu, mx, o));
        float sm = 0.f;
        for (int p = beg + lane; p < end; p += 32) {
            float ex = __expf(g_ex2[p] - mx);
            g_ex2[p] = ex;
            sm += ex;
        }
#pragma unroll
        for (int o = 16; o > 0; o >>= 1) sm += __shfl_xor_sync(0xffffffffu, sm, o);
        float inv = 1.f / (sm + EPSV);
        __syncwarp();
        for (int p = beg; p < end; ++p) {
            int s = g_csrc[p];
            float alpha = g_ex2[p] * inv;
            float2 hv = *(const float2*)&g_h2[(size_t)s * CO + lane * 2];
            acc.x = fmaf(hv.x, alpha, acc.x);
            acc.y = fmaf(hv.y, alpha, acc.y);
        }
    }

    float2 b = *(const float2*)&b2[lane * 2];
    *(float2*)&out[(size_t)n * CO + lane * 2] = make_float2(acc.x + b.x, acc.y + b.y);
}

// ---------------- launcher -------------------------------------------------------
extern "C" void kernel_launch(void* const* d_in, const int* in_sizes, int n_in,
                              void* d_out, int out_size) {
    const float* x   = (const float*)d_in[0];
    const void*  ei  = d_in[1];
    const float* W1  = (const float*)d_in[2];
    const float* as1 = (const float*)d_in[3];
    const float* ad1 = (const float*)d_in[4];
    const float* b1  = (const float*)d_in[5];
    const float* W2  = (const float*)d_in[6];
    const float* as2 = (const float*)d_in[7];
    const float* ad2 = (const float*)d_in[8];
    const float* b2  = (const float*)d_in[9];
    float* out = (float*)d_out;

    (void)in_sizes; (void)n_in; (void)out_size;

    const int gNode  = (NNODES + TPB - 1) / TPB;
    const int gStats = (NNODES * NH1 + TPB - 1) / TPB;
    const int gEdge  = (ETOT + TPB - 1) / TPB;
    const int gWarp  = (int)(((long long)NNODES * 32 + TPB - 1) / TPB);

    // CSR build
    k_zero_deg<<<gNode, TPB>>>();
    k_prep<<<gEdge, TPB>>>(ei);
    k_scan1<<<NB1, SCAN_B>>>();
    k_scan2<<<1, 256>>>();
    k_scan3<<<gNode, TPB>>>();
    k_scatter<<<gEdge, TPB>>>();

    // layer 1
    gemm1_kernel<<<(NNODES + 127) / 128, 256>>>(x, W1);
    k_att1<<<gStats, TPB>>>(as1, ad1);
    k_l1<<<gWarp, TPB>>>(b1);

    // layer 2
    gemm2_kernel<<<(NNODES + 127) / 128, 256>>>(W2);
    k_att2<<<gNode, TPB>>>(as2, ad2);
    k_l2<<<gWarp, TPB>>>(b2, out);
}